// round 10
// baseline (speedup 1.0000x reference)
#include <cuda_runtime.h>

#define NMAX 100000
#define EMAX 1600000
#define NG 64
#define NH 64

// ---- scratch (static device globals; no allocations allowed) ----
__device__ __align__(16) float g_h[(size_t)NMAX * NH];
__device__ __align__(16) float g_out[(size_t)NMAX * NH];
__device__ float g_dinv[NMAX];
__device__ float g_selfw[NMAX];          // 1/deg  (= dinv^2)
__device__ int   g_cnt[NMAX];
__device__ int   g_rowptr[NMAX + 1];
__device__ int   g_cursor[NMAX];
__device__ int   g_csr_src[EMAX];
__device__ float g_csr_norm[EMAX];
__device__ float g_pooled[NG * NH];

// ---------------- CSR build: histogram -> scan -> place ----------------

__global__ void k_zero_cnt(int n) {
    int i = blockIdx.x * blockDim.x + threadIdx.x;
    if (i < n) g_cnt[i] = 0;
}

__global__ void k_count(const int* __restrict__ ei, int E, int n) {
    int e = blockIdx.x * blockDim.x + threadIdx.x;
    if (e < E) {
        int d = ei[(size_t)E + e];
        d = d < 0 ? 0 : (d >= n ? n - 1 : d);
        atomicAdd(&g_cnt[d], 1);
    }
}

// single-block exclusive scan over counts; also emits rowptr, cursor, dinv, selfw
__global__ void __launch_bounds__(1024) k_scan(int n, int E) {
    __shared__ int ssum[1024];
    const int tid = threadIdx.x;
    const int per = (n + 1023) / 1024;
    const int start = tid * per;
    const int end   = min(start + per, n);

    int s = 0;
    for (int i = start; i < end; i++) s += g_cnt[i];
    ssum[tid] = s;
    __syncthreads();

    // Hillis-Steele inclusive scan
    for (int d = 1; d < 1024; d <<= 1) {
        int v = (tid >= d) ? ssum[tid - d] : 0;
        __syncthreads();
        ssum[tid] += v;
        __syncthreads();
    }
    int off = ssum[tid] - s;   // exclusive prefix for this thread's chunk

    for (int i = start; i < end; i++) {
        int c = g_cnt[i];
        g_rowptr[i] = off;
        g_cursor[i] = off;
        float deg = (float)(c + 1);          // self-loop included
        float di  = rsqrtf(deg);
        g_dinv[i]  = di;
        g_selfw[i] = 1.0f / deg;             // dinv^2 exactly
        off += c;
    }
    if (tid == 1023) g_rowptr[n] = E;
}

__global__ void k_place(const int* __restrict__ ei, int E, int n) {
    int e = blockIdx.x * blockDim.x + threadIdx.x;
    if (e < E) {
        int s = ei[e];
        int d = ei[(size_t)E + e];
        s = s < 0 ? 0 : (s >= n ? n - 1 : s);
        d = d < 0 ? 0 : (d >= n ? n - 1 : d);
        int pos = atomicAdd(&g_cursor[d], 1);
        g_csr_src[pos]  = s;
        g_csr_norm[pos] = g_dinv[s] * g_dinv[d];
    }
}

// ---------------- GEMM: H[n,64] = X[n,K] @ W[K,64] ----------------

template<int K, bool USE_GOUT>
__global__ void __launch_bounds__(256) k_gemm(const float* __restrict__ Xin,
                                              const float* __restrict__ W, int n) {
    __shared__ float Ws[64 * 64];
    __shared__ float Xs[64 * 68];

    const float* __restrict__ X = USE_GOUT ? (const float*)g_out : Xin;
    const int tid  = threadIdx.x;
    const int row0 = blockIdx.x * 64;
    const int r = (tid >> 4) << 2;
    const int c = (tid & 15) << 2;

    float acc[4][4] = {};

    for (int kc = 0; kc < K; kc += 64) {
        for (int i = tid; i < 64 * 16; i += 256)
            ((float4*)Ws)[i] = ((const float4*)(W + (size_t)kc * 64))[i];
        for (int i = tid; i < 64 * 16; i += 256) {
            int rr = i >> 4, c4 = i & 15;
            float4 v = make_float4(0.f, 0.f, 0.f, 0.f);
            if (row0 + rr < n)
                v = *((const float4*)(X + (size_t)(row0 + rr) * K + kc + c4 * 4));
            *((float4*)(Xs + rr * 68 + c4 * 4)) = v;
        }
        __syncthreads();

        #pragma unroll 16
        for (int k = 0; k < 64; k++) {
            float4 wb = *((const float4*)(Ws + k * 64 + c));
            float a0 = Xs[(r + 0) * 68 + k];
            float a1 = Xs[(r + 1) * 68 + k];
            float a2 = Xs[(r + 2) * 68 + k];
            float a3 = Xs[(r + 3) * 68 + k];
            acc[0][0] += a0 * wb.x; acc[0][1] += a0 * wb.y; acc[0][2] += a0 * wb.z; acc[0][3] += a0 * wb.w;
            acc[1][0] += a1 * wb.x; acc[1][1] += a1 * wb.y; acc[1][2] += a1 * wb.z; acc[1][3] += a1 * wb.w;
            acc[2][0] += a2 * wb.x; acc[2][1] += a2 * wb.y; acc[2][2] += a2 * wb.z; acc[2][3] += a2 * wb.w;
            acc[3][0] += a3 * wb.x; acc[3][1] += a3 * wb.y; acc[3][2] += a3 * wb.z; acc[3][3] += a3 * wb.w;
        }
        __syncthreads();
    }

    #pragma unroll
    for (int i = 0; i < 4; i++) {
        int rr = row0 + r + i;
        if (rr < n)
            *((float4*)(g_h + (size_t)rr * 64 + c)) =
                make_float4(acc[i][0], acc[i][1], acc[i][2], acc[i][3]);
    }
}

// ---------------- fused aggregate + self-loop + bias + relu ----------------
// One 16-lane group per node; lane l owns float4 features [4l, 4l+4).
// acc = sum_e norm[e] * h[src[e]]; out = relu(acc + h[d]/deg + b).

__global__ void __launch_bounds__(256) k_agg(const float* __restrict__ bias, int n) {
    const int node = blockIdx.x * 16 + (threadIdx.x >> 4);
    const int l = threadIdx.x & 15;
    if (node >= n) return;

    const int beg = g_rowptr[node];
    const int end = g_rowptr[node + 1];

    float4 acc = make_float4(0.f, 0.f, 0.f, 0.f);
    int e = beg;
    for (; e + 1 < end; e += 2) {
        int   s0 = g_csr_src[e],     s1 = g_csr_src[e + 1];
        float n0 = g_csr_norm[e],    n1 = g_csr_norm[e + 1];
        float4 v0 = *((const float4*)(g_h + (size_t)s0 * 64 + l * 4));
        float4 v1 = *((const float4*)(g_h + (size_t)s1 * 64 + l * 4));
        acc.x = fmaf(v0.x, n0, acc.x); acc.y = fmaf(v0.y, n0, acc.y);
        acc.z = fmaf(v0.z, n0, acc.z); acc.w = fmaf(v0.w, n0, acc.w);
        acc.x = fmaf(v1.x, n1, acc.x); acc.y = fmaf(v1.y, n1, acc.y);
        acc.z = fmaf(v1.z, n1, acc.z); acc.w = fmaf(v1.w, n1, acc.w);
    }
    if (e < end) {
        int   s0 = g_csr_src[e];
        float n0 = g_csr_norm[e];
        float4 v0 = *((const float4*)(g_h + (size_t)s0 * 64 + l * 4));
        acc.x = fmaf(v0.x, n0, acc.x); acc.y = fmaf(v0.y, n0, acc.y);
        acc.z = fmaf(v0.z, n0, acc.z); acc.w = fmaf(v0.w, n0, acc.w);
    }

    float sw = g_selfw[node];
    float4 hd = *((const float4*)(g_h + (size_t)node * 64 + l * 4));
    float b0 = bias[l * 4 + 0], b1 = bias[l * 4 + 1];
    float b2 = bias[l * 4 + 2], b3 = bias[l * 4 + 3];
    float4 o;
    o.x = fmaxf(fmaf(hd.x, sw, acc.x) + b0, 0.f);
    o.y = fmaxf(fmaf(hd.y, sw, acc.y) + b1, 0.f);
    o.z = fmaxf(fmaf(hd.z, sw, acc.z) + b2, 0.f);
    o.w = fmaxf(fmaf(hd.w, sw, acc.w) + b3, 0.f);
    *((float4*)(g_out + (size_t)node * 64 + l * 4)) = o;
}

// ---------------- mean-pool per graph (batch sorted -> binary search) ----------------

__device__ __forceinline__ int lower_bound_i(const int* b, int n, int v) {
    int lo = 0, hi = n;
    while (lo < hi) {
        int m = (lo + hi) >> 1;
        if (b[m] < v) lo = m + 1; else hi = m;
    }
    return lo;
}

__global__ void k_pool(const int* __restrict__ batch, int n) {
    __shared__ int s_bounds[2];
    __shared__ float red[256];
    int g = blockIdx.x;
    if (threadIdx.x == 0) {
        s_bounds[0] = lower_bound_i(batch, n, g);
        s_bounds[1] = lower_bound_i(batch, n, g + 1);
    }
    __syncthreads();
    int start = s_bounds[0], end = s_bounds[1];
    int f = threadIdx.x & 63, j = threadIdx.x >> 6;
    float acc = 0.f;
    for (int node = start + j; node < end; node += 4)
        acc += g_out[(size_t)node * 64 + f];
    red[threadIdx.x] = acc;
    __syncthreads();
    if (j == 0) {
        float s = red[f] + red[64 + f] + red[128 + f] + red[192 + f];
        float cnt = (float)(end - start);
        g_pooled[g * 64 + f] = s / fmaxf(cnt, 1.0f);
    }
}

// ---------------- final linear + softmax ----------------

__global__ void k_final(const float* __restrict__ Wl, const float* __restrict__ bl,
                        float* __restrict__ out) {
    int g = threadIdx.x;
    if (g >= NG) return;
    float p[64];
    #pragma unroll
    for (int f = 0; f < 64; f++) p[f] = g_pooled[g * 64 + f];
    float logits[10];
    #pragma unroll
    for (int c = 0; c < 10; c++) {
        float s = bl[c];
        #pragma unroll
        for (int f = 0; f < 64; f++) s += p[f] * Wl[f * 10 + c];
        logits[c] = s;
    }
    float m = logits[0];
    #pragma unroll
    for (int c = 1; c < 10; c++) m = fmaxf(m, logits[c]);
    float sum = 0.f;
    #pragma unroll
    for (int c = 0; c < 10; c++) { logits[c] = expf(logits[c] - m); sum += logits[c]; }
    float inv = 1.0f / sum;
    #pragma unroll
    for (int c = 0; c < 10; c++) out[g * 10 + c] = logits[c] * inv;
}

// ---------------- launch ----------------
// Inputs bound BY ELEMENT COUNT. edge_index/batch are int32 (JAX x64-disabled).

extern "C" void kernel_launch(void* const* d_in, const int* in_sizes, int n_in,
                              void* d_out, int out_size) {
    (void)out_size;
    const float* x = nullptr;
    const int* ei = nullptr;
    const int* batch = nullptr;
    const float *W1 = nullptr, *W2 = nullptr, *W3 = nullptr, *Wl = nullptr;
    const float *b1 = nullptr, *b2 = nullptr, *b3 = nullptr, *bl = nullptr;
    int ei_elems = 0, batch_elems = 0;
    int n4096 = 0, n64 = 0;

    for (int i = 0; i < n_in; i++) {
        int sz = in_sizes[i];
        const void* p = d_in[i];
        if (sz == 100000 * 128)      x = (const float*)p;
        else if (sz == 2 * 1600000)  { ei = (const int*)p; ei_elems = sz; }
        else if (sz == 100000)       { batch = (const int*)p; batch_elems = sz; }
        else if (sz == 128 * 64)     W1 = (const float*)p;
        else if (sz == 64 * 64)      { if (n4096++ == 0) W2 = (const float*)p; else W3 = (const float*)p; }
        else if (sz == 64)           { if (n64 == 0) b1 = (const float*)p;
                                       else if (n64 == 1) b2 = (const float*)p;
                                       else b3 = (const float*)p; n64++; }
        else if (sz == 64 * 10)      Wl = (const float*)p;
        else if (sz == 10)           bl = (const float*)p;
    }
    if (!x || !ei || !batch || !W1 || !W2 || !W3 || !b1 || !b2 || !b3 || !Wl || !bl)
        return;

    int n = batch_elems;     if (n > NMAX) n = NMAX;
    int E = ei_elems / 2;    if (E > EMAX) E = EMAX;

    const int TB = 256;
    const int nbN  = (n + TB - 1) / TB;
    const int nbE  = (E + TB - 1) / TB;
    const int nbGm = (n + 63) / 64;
    const int nbAg = (n + 15) / 16;

    // CSR build (by dst) + norms
    k_zero_cnt<<<nbN, TB>>>(n);
    k_count<<<nbE, TB>>>(ei, E, n);
    k_scan<<<1, 1024>>>(n, E);
    k_place<<<nbE, TB>>>(ei, E, n);

    // layer 1 (K=128, input = x)
    k_gemm<128, false><<<nbGm, TB>>>(x, W1, n);
    k_agg<<<nbAg, TB>>>(b1, n);

    // layer 2
    k_gemm<64, true><<<nbGm, TB>>>(nullptr, W2, n);
    k_agg<<<nbAg, TB>>>(b2, n);

    // layer 3
    k_gemm<64, true><<<nbGm, TB>>>(nullptr, W3, n);
    k_agg<<<nbAg, TB>>>(b3, n);

    // pool + classify
    k_pool<<<NG, TB>>>(batch, n);
    k_final<<<1, 64>>>(Wl, bl, (float*)d_out);
}